// round 9
// baseline (speedup 1.0000x reference)
#include <cuda_runtime.h>
#include <cmath>
#include <complex>
#include <cstring>

// Problem constants
#define TT   50
#define PAD  49
#define EXT  148              // PAD + TT + PAD
#define BB   50
#define CC   4096
#define BC   (BB * CC)        // 204800 channels
#define NSEC 2
#define NBAND 2
#define CTILE 8               // channels (c) per block
#define BLKT (BB * CTILE)     // 400 threads: thread (b, c_local)

struct FiltCoef {
    // [band][section]
    float b0[NBAND][NSEC];
    float b2[NBAND][NSEC];
    float a1[NBAND][NSEC];
    float a2[NBAND][NSEC];
    float zi0[NBAND][NSEC];
    float zi1[NBAND][NSEC];
};

__global__ void __launch_bounds__(BLKT)
fused_kernel(const float* __restrict__ x, float* __restrict__ out, FiltCoef cf) {
    __shared__ float s_m2 [TT][CTILE];
    __shared__ float s_inv[TT][CTILE];

    const int tid  = threadIdx.x;          // < 400
    const int b    = tid >> 3;             // 0..49  (batch index == stat provider for t=b)
    const int cl   = tid & (CTILE - 1);    // 0..7
    const int band = blockIdx.x;
    const int c    = blockIdx.y * CTILE + cl;
    const int ch   = b * CC + c;           // channel in [0, BC)
    const float* xc = x + ch;

    const float b00 = cf.b0[band][0], b20 = cf.b2[band][0];
    const float a10 = cf.a1[band][0], a20 = cf.a2[band][0];
    const float b01 = cf.b0[band][1], b21 = cf.b2[band][1];
    const float a11 = cf.a1[band][1], a21 = cf.a2[band][1];

    // y for ext indices [PAD, EXT) lives in registers (fully unrolled indexing)
    float arr[EXT - PAD];   // 99 floats

    const float x0 = xc[0];
    const float xl = xc[(size_t)(TT - 1) * BC];
    const float tx0 = 2.0f * x0;
    const float txl = 2.0f * xl;

    // ---- forward pass (2 cascaded biquads, DF2T) over the odd extension ----
    {
        const float e0 = tx0 - xc[(size_t)PAD * BC];   // ext[0] = 2*x0 - x[PAD]
        float z00 = cf.zi0[band][0] * e0, z01 = cf.zi1[band][0] * e0;
        float z10 = cf.zi0[band][1] * e0, z11 = cf.zi1[band][1] * e0;

        // left mirror: t = 0..PAD-1, xt = 2*x0 - x[PAD-t]  (state only, no storage)
        #pragma unroll
        for (int t = 0; t < PAD; t++) {
            const float xt = tx0 - xc[(size_t)(PAD - t) * BC];
            const float y0 = fmaf(b00, xt, z00);
            z00 = fmaf(-a10, y0, z01);
            z01 = fmaf(b20, xt, -a20 * y0);
            const float y1 = fmaf(b01, y0, z10);
            z10 = fmaf(-a11, y1, z11);
            z11 = fmaf(b21, y0, -a21 * y1);
        }
        // central: xt = x[t], store y
        #pragma unroll
        for (int t = 0; t < TT; t++) {
            const float xt = xc[(size_t)t * BC];
            const float y0 = fmaf(b00, xt, z00);
            z00 = fmaf(-a10, y0, z01);
            z01 = fmaf(b20, xt, -a20 * y0);
            const float y1 = fmaf(b01, y0, z10);
            z10 = fmaf(-a11, y1, z11);
            z11 = fmaf(b21, y0, -a21 * y1);
            arr[t] = y1;
        }
        // right mirror: xt = 2*xl - x[TT-1-k], store y
        #pragma unroll
        for (int k = 1; k <= PAD; k++) {
            const float xt = txl - xc[(size_t)(TT - 1 - k) * BC];
            const float y0 = fmaf(b00, xt, z00);
            z00 = fmaf(-a10, y0, z01);
            z01 = fmaf(b20, xt, -a20 * y0);
            const float y1 = fmaf(b01, y0, z10);
            z10 = fmaf(-a11, y1, z11);
            z11 = fmaf(b21, y0, -a21 * y1);
            arr[TT - 1 + k] = y1;
        }
    }

    // ---- backward pass: filter reversed y from ext index EXT-1 down to PAD ----
    // (steps below PAD only produce discarded outputs; backward state flows
    //  right-to-left, so those steps cannot affect the central outputs)
    {
        const float e = arr[EXT - PAD - 1];   // y at ext index EXT-1
        float z00 = cf.zi0[band][0] * e, z01 = cf.zi1[band][0] * e;
        float z10 = cf.zi0[band][1] * e, z11 = cf.zi1[band][1] * e;
        #pragma unroll
        for (int i = 0; i < EXT - PAD; i++) {   // slot 98 down to 0
            const int s = EXT - PAD - 1 - i;
            const float xt = arr[s];
            const float y0 = fmaf(b00, xt, z00);
            z00 = fmaf(-a10, y0, z01);
            z01 = fmaf(b20, xt, -a20 * y0);
            const float y1 = fmaf(b01, y0, z10);
            z10 = fmaf(-a11, y1, z11);
            z11 = fmaf(b21, y0, -a21 * y1);
            if (s < TT) arr[s] = y1;   // central outputs, correct time order
        }
    }

    // ---- first demean over T (per-channel), compute own stats ----
    float s = 0.0f;
    #pragma unroll
    for (int t = 0; t < TT; t++) s += arr[t];
    const float m = s * (1.0f / TT);

    float s2 = 0.0f;
    #pragma unroll
    for (int t = 0; t < TT; t++) {
        const float yd = arr[t] - m;
        arr[t] = yd;
        s2 += yd;
    }
    const float m2 = s2 * (1.0f / TT);

    float v = 0.0f;
    #pragma unroll
    for (int t = 0; t < TT; t++) {
        const float d = arr[t] - m2;
        v = fmaf(d, d, v);
    }

    // publish this channel's stats: it is the provider for time index t = b
    s_m2 [b][cl] = m2;
    s_inv[b][cl] = rsqrtf(v * (1.0f / (TT - 1)));
    __syncthreads();

    // ---- normalize with stats of channel (b'=t, c) and write final output ----
    // (mirrors the reference's (T,B,C)-(B,1,C) broadcasting quirk; T==B)
    float* ob = out + (size_t)band * TT * BC + ch;
    #pragma unroll
    for (int t = 0; t < TT; t++)
        ob[(size_t)t * BC] = (arr[t] - s_m2[t][cl]) * s_inv[t][cl];
}

// ---------------- host-side filter design (mirrors reference numpy code) ----------------
static void design_band(double w1, double w2, double sos[NSEC][6], double zi[NSEC][2]) {
    using cd = std::complex<double>;
    const double PI = 3.14159265358979323846;
    const double fs = 2.0;
    const double W1 = 2.0 * fs * tan(PI * w1 / fs);
    const double W2 = 2.0 * fs * tan(PI * w2 / fs);
    const double bw = W2 - W1;
    const double wo = sqrt(W1 * W2);

    cd p_bp[4];
    for (int k = 1; k <= 2; k++) {
        cd p = -std::exp(cd(0.0, PI * (2 * k - 1) / 4.0));
        cd plp = p * (bw / 2.0);
        cd disc = std::sqrt(plp * plp - cd(wo * wo, 0.0));
        p_bp[k - 1] = plp + disc;
        p_bp[k + 1] = plp - disc;
    }
    const double fs2 = 2.0 * fs;   // 4.0
    cd prod(1.0, 0.0);
    for (int i = 0; i < 4; i++) prod *= (cd(fs2, 0.0) - p_bp[i]);
    const double gain = bw * bw * fs2 * fs2 / prod.real();

    cd pos[2];
    int npos = 0;
    for (int i = 0; i < 4; i++) {
        cd pd = (cd(fs2, 0.0) + p_bp[i]) / (cd(fs2, 0.0) - p_bp[i]);
        if (pd.imag() > 0.0 && npos < 2) pos[npos++] = pd;
    }
    for (int s = 0; s < NSEC; s++) {
        const double g = (s == 0) ? gain : 1.0;
        sos[s][0] = g;  sos[s][1] = 0.0;  sos[s][2] = -g;
        sos[s][3] = 1.0;
        sos[s][4] = -2.0 * pos[s].real();
        sos[s][5] = std::norm(pos[s]);
    }
    // sosfilt_zi
    double scale = 1.0;
    for (int s = 0; s < NSEC; s++) {
        const double b0 = sos[s][0], b1 = sos[s][1], b2 = sos[s][2];
        const double a1 = sos[s][4], a2 = sos[s][5];
        const double B0 = b1 - a1 * b0;
        const double B1 = b2 - a2 * b0;
        const double det = 1.0 + a1 + a2;
        zi[s][0] = scale * (B0 + B1) / det;
        zi[s][1] = scale * ((1.0 + a1) * B1 - a2 * B0) / det;
        scale *= (b0 + b1 + b2) / (1.0 + a1 + a2);
    }
}

extern "C" void kernel_launch(void* const* d_in, const int* in_sizes, int n_in,
                              void* d_out, int out_size) {
    const float* x = (const float*)d_in[0];
    float* out = (float*)d_out;

    const double bands[NBAND][2] = { {0.05, 0.15}, {0.2, 0.4} };
    FiltCoef cf;
    for (int b = 0; b < NBAND; b++) {
        double sos[NSEC][6], zi[NSEC][2];
        design_band(bands[b][0], bands[b][1], sos, zi);
        for (int s = 0; s < NSEC; s++) {
            cf.b0[b][s]  = (float)sos[s][0];
            cf.b2[b][s]  = (float)sos[s][2];
            cf.a1[b][s]  = (float)sos[s][4];
            cf.a2[b][s]  = (float)sos[s][5];
            cf.zi0[b][s] = (float)zi[s][0];
            cf.zi1[b][s] = (float)zi[s][1];
        }
    }

    // band on x so the two bands of the same c-tile are launch-adjacent
    // (x input read hits L2 for the second band)
    dim3 grid(NBAND, CC / CTILE);          // 2 x 512
    fused_kernel<<<grid, BLKT>>>(x, out, cf);
}